// round 7
// baseline (speedup 1.0000x reference)
#include <cuda_runtime.h>
#include <math.h>

// Problem constants
#define N_RES 2048
#define D_IN  128
#define T_SEQ 2048
#define GRID  128      // CTAs, all wave-1 resident (weights live in registers)
#define ROWS  16       // reservoir rows per CTA (one per warp)
#define NTH   512      // 16 warps; each warp owns a 128-column chunk, each lane 4 cols
#define SP_STRIDE 18   // sPart row stride: 8B-aligned float2 reads, conflict-free writes

// Scratch (allocation-free rule: __device__ globals)
__device__ float              g_U[(size_t)T_SEQ * N_RES];  // 16 MB: input @ W_in^T
__device__ unsigned long long g_Xtag[2][N_RES];            // (value,tag) pairs, parity-buffered

// Reset tags every launch (graph replay would otherwise see stale matching tags)
__global__ void esn_zero_kernel() {
    int i = blockIdx.x * blockDim.x + threadIdx.x;
    if (i < 2 * N_RES) ((unsigned long long*)g_Xtag)[i] = 0ull;
}

__device__ __forceinline__ unsigned long long ld_acq64(const unsigned long long* p) {
    unsigned long long v;
    asm volatile("ld.acquire.gpu.global.u64 %0, [%1];" : "=l"(v) : "l"(p) : "memory");
    return v;
}
__device__ __forceinline__ void st_rel64(unsigned long long* p, unsigned long long v) {
    asm volatile("st.release.gpu.global.u64 [%0], %1;" :: "l"(p), "l"(v) : "memory");
}
__device__ __forceinline__ unsigned long long ffma2(unsigned long long a,
                                                    unsigned long long b,
                                                    unsigned long long c) {
    unsigned long long d;
    asm("fma.rn.f32x2 %0, %1, %2, %3;" : "=l"(d) : "l"(a), "l"(b), "l"(c));
    return d;
}
__device__ __forceinline__ float hadd2(unsigned long long a) {
    unsigned lo, hi;
    asm("mov.b64 {%0,%1}, %2;" : "=r"(lo), "=r"(hi) : "l"(a));
    return __uint_as_float(lo) + __uint_as_float(hi);
}
__device__ __forceinline__ unsigned long long pack2(unsigned lo, unsigned hi) {
    unsigned long long v;
    asm("mov.b64 %0, {%1,%2};" : "=l"(v) : "r"(lo), "r"(hi));
    return v;
}

__global__ void __launch_bounds__(NTH, 1)
esn_kernel(const float* __restrict__ inp,    // (T, D_IN)
           const float* __restrict__ Win,    // (N_RES, D_IN)
           const float* __restrict__ Wres,   // (N_RES, N_RES)
           float*       __restrict__ out)    // (T, N_RES)
{
    __shared__ float sWin[ROWS * D_IN];             // prologue only
    __shared__ float sPart[2][ROWS * SP_STRIDE];    // parity-buffered partials

    const int tid  = threadIdx.x;
    const int bid  = blockIdx.x;
    const int row0 = bid * ROWS;
    const int warp = tid >> 5;
    const int lane = tid & 31;
    const int cb   = warp * 128 + lane * 4;         // this thread's 4-column base
    // bit-reversed 4-bit lane -> row map for the merged butterfly
    const int rowmap = ((lane & 1) << 3) | ((lane & 2) << 1)
                     | ((lane & 4) >> 1) | ((lane & 8) >> 3);

    // ---- stage W_in slice into SMEM ----
    for (int i = tid; i < ROWS * D_IN; i += NTH)
        sWin[i] = Win[(size_t)row0 * D_IN + i];
    __syncthreads();

    // ---- prologue: U[t][row0..row0+15] for all t ----
    for (int it = 0; it < T_SEQ / NTH; ++it) {
        const int t = it * NTH + tid;
        float acc[ROWS];
        #pragma unroll
        for (int r = 0; r < ROWS; ++r) acc[r] = 0.f;
        #pragma unroll
        for (int c = 0; c < 4; ++c) {
            float4 xin[8];
            const float4* ip = (const float4*)(inp + (size_t)t * D_IN + c * 32);
            #pragma unroll
            for (int k = 0; k < 8; ++k) xin[k] = ip[k];
            #pragma unroll
            for (int r = 0; r < ROWS; ++r) {
                const float4* wr = (const float4*)(sWin + r * D_IN + c * 32);
                #pragma unroll
                for (int k = 0; k < 8; ++k) {
                    float4 w = wr[k];
                    acc[r] += w.x * xin[k].x + w.y * xin[k].y
                            + w.z * xin[k].z + w.w * xin[k].w;
                }
            }
        }
        #pragma unroll
        for (int r = 0; r < ROWS; ++r)
            g_U[(size_t)t * N_RES + row0 + r] = acc[r];
    }

    // ---- W_res slice into registers: 16 rows x 4 cols = 64 regs (packed f32x2) ----
    unsigned long long wv[ROWS][2];
    #pragma unroll
    for (int r = 0; r < ROWS; ++r) {
        ulonglong2 q = *(const ulonglong2*)(Wres + (size_t)(row0 + r) * N_RES + cb);
        wv[r][0] = q.x; wv[r][1] = q.y;
    }
    __syncthreads();   // g_U complete & visible CTA-wide

    const float cns = 0.022097086912079612f;  // 1/sqrt(2048)

    for (int t = 0; t < T_SEQ; ++t) {
        const int par = t & 1;

        float uval = 0.f;
        if (lane == 0)
            uval = __ldcg(g_U + (size_t)t * N_RES + row0 + warp);   // early, independent

        if (t > 0) {
            // ---- poll this thread's 4 tagged x_{t-1} words (data IS the flag) ----
            const unsigned long long* src = &g_Xtag[(t - 1) & 1][cb];
            const unsigned exp = (unsigned)t;   // producer stored tag = (t-1)+1
            unsigned long long q0, q1, q2, q3;
            do {
                q0 = ld_acq64(src + 0); q1 = ld_acq64(src + 1);
                q2 = ld_acq64(src + 2); q3 = ld_acq64(src + 3);
            } while ((unsigned)(q0 >> 32) != exp || (unsigned)(q1 >> 32) != exp ||
                     (unsigned)(q2 >> 32) != exp || (unsigned)(q3 >> 32) != exp);

            const unsigned long long v01 = pack2((unsigned)q0, (unsigned)q1);
            const unsigned long long v23 = pack2((unsigned)q2, (unsigned)q3);

            // ---- 16 rows x 2 packed FMAs ----
            float p[ROWS];
            #pragma unroll
            for (int r = 0; r < ROWS; ++r) {
                unsigned long long a = ffma2(wv[r][1], v23, 0ull);
                a = ffma2(wv[r][0], v01, a);
                p[r] = hadd2(a);
            }

            // ---- merged butterfly: 16 sums across 32 lanes in 16 SHFLs ----
            #pragma unroll
            for (int i = 0; i < 8; ++i) {   // m = 1
                float send = (lane & 1) ? p[i] : p[i + 8];
                float recv = __shfl_xor_sync(0xffffffffu, send, 1);
                p[i] = ((lane & 1) ? p[i + 8] : p[i]) + recv;
            }
            #pragma unroll
            for (int i = 0; i < 4; ++i) {   // m = 2
                float send = (lane & 2) ? p[i] : p[i + 4];
                float recv = __shfl_xor_sync(0xffffffffu, send, 2);
                p[i] = ((lane & 2) ? p[i + 4] : p[i]) + recv;
            }
            #pragma unroll
            for (int i = 0; i < 2; ++i) {   // m = 4
                float send = (lane & 4) ? p[i] : p[i + 2];
                float recv = __shfl_xor_sync(0xffffffffu, send, 4);
                p[i] = ((lane & 4) ? p[i + 2] : p[i]) + recv;
            }
            {                               // m = 8
                float send = (lane & 8) ? p[0] : p[1];
                float recv = __shfl_xor_sync(0xffffffffu, send, 8);
                p[0] = ((lane & 8) ? p[1] : p[0]) + recv;
            }
            p[0] += __shfl_xor_sync(0xffffffffu, p[0], 16);   // fold upper half-warp

            if (lane < 16)
                sPart[par][rowmap * SP_STRIDE + warp] = p[0];
        }
        __syncthreads();

        // ---- warp w finishes row w: lane 0 sums 16 partials, erf, publish ----
        if (lane == 0) {
            float pre = uval;
            if (t > 0) {
                const float2* pp = (const float2*)(sPart[par] + warp * SP_STRIDE);
                float2 a0 = pp[0], a1 = pp[1], a2 = pp[2], a3 = pp[3];
                float2 a4 = pp[4], a5 = pp[5], a6 = pp[6], a7 = pp[7];
                float s0 = (a0.x + a0.y) + (a1.x + a1.y);
                float s1 = (a2.x + a2.y) + (a3.x + a3.y);
                float s2 = (a4.x + a4.y) + (a5.x + a5.y);
                float s3 = (a6.x + a6.y) + (a7.x + a7.y);
                pre += (s0 + s1) + (s2 + s3);
            }
            const float xv = erff(pre) * cns;
            __stcg(out + (size_t)t * N_RES + row0 + warp, xv);
            st_rel64(&g_Xtag[par][row0 + warp],
                     pack2(__float_as_uint(xv), (unsigned)(t + 1)));
        }
        // no second barrier: sPart is parity-buffered; the tag chain guarantees
        // >=2-step separation before any same-parity rewrite
    }
}

extern "C" void kernel_launch(void* const* d_in, const int* in_sizes, int n_in,
                              void* d_out, int out_size) {
    const float* inp  = (const float*)d_in[0];   // input_data (2048,128)
    const float* Win  = (const float*)d_in[1];   // W_in       (2048,128)
    const float* Wres = (const float*)d_in[2];   // W_res      (2048,2048)
    float* out = (float*)d_out;                  // (2048,2048) float32

    esn_zero_kernel<<<4, 1024>>>();
    esn_kernel<<<GRID, NTH>>>(inp, Win, Wres, out);
}

// round 9
// speedup vs baseline: 2.2357x; 2.2357x over previous
#include <cuda_runtime.h>
#include <math.h>

// Problem constants
#define N_RES 2048
#define D_IN  128
#define T_SEQ 2048
#define GRID  128      // CTAs, all wave-1 resident (weights fill the whole RF)
#define ROWS  16       // reservoir rows per CTA
#define NTH   512      // 16 warps = 2 row-groups (8 rows) x 8 column-chunks (256 cols)
#define SP_STRIDE 10   // sPart row stride (conflict-free finisher float2 reads)

// Scratch (allocation-free rule: __device__ globals)
__device__ float    g_U[(size_t)T_SEQ * N_RES];  // 16 MB: input @ W_in^T
__device__ unsigned g_flags[GRID * 32];          // per-CTA step flag, 128B stride

__global__ void esn_zero_kernel() {
    int i = blockIdx.x * blockDim.x + threadIdx.x;
    if (i < GRID * 32) g_flags[i] = 0u;
}

__device__ __forceinline__ unsigned ld_acq(const unsigned* p) {
    unsigned v;
    asm volatile("ld.acquire.gpu.global.u32 %0, [%1];" : "=r"(v) : "l"(p) : "memory");
    return v;
}
__device__ __forceinline__ void st_rel(unsigned* p, unsigned v) {
    asm volatile("st.release.gpu.global.u32 [%0], %1;" :: "l"(p), "r"(v) : "memory");
}
__device__ __forceinline__ unsigned long long ffma2(unsigned long long a,
                                                    unsigned long long b,
                                                    unsigned long long c) {
    unsigned long long d;
    asm("fma.rn.f32x2 %0, %1, %2, %3;" : "=l"(d) : "l"(a), "l"(b), "l"(c));
    return d;
}
__device__ __forceinline__ float hadd2(unsigned long long a) {
    unsigned lo, hi;
    asm("mov.b64 {%0,%1}, %2;" : "=r"(lo), "=r"(hi) : "l"(a));
    return __uint_as_float(lo) + __uint_as_float(hi);
}
__device__ __forceinline__ void ldcg_v2u64(const void* p,
                                           unsigned long long& a, unsigned long long& b) {
    asm volatile("ld.global.cg.v2.u64 {%0,%1}, [%2];" : "=l"(a), "=l"(b) : "l"(p));
}

__global__ void __launch_bounds__(NTH, 1)
esn_kernel(const float* __restrict__ inp,    // (T, D_IN)
           const float* __restrict__ Win,    // (N_RES, D_IN)
           const float* __restrict__ Wres,   // (N_RES, N_RES)
           float*       __restrict__ out)    // (T, N_RES)
{
    __shared__ float sWin[ROWS * D_IN];          // prologue only
    __shared__ float sPart[ROWS * SP_STRIDE];    // [row][chunk] partials

    const int tid  = threadIdx.x;
    const int bid  = blockIdx.x;
    const int row0 = bid * ROWS;
    const int warp = tid >> 5;
    const int lane = tid & 31;
    const int g    = warp & 1;                   // row-group: rows 8g..8g+7
    const int cch  = warp >> 1;                  // column-chunk: cols 256*cch..+255
    const int cb   = cch * 256 + lane * 8;       // this thread's 8-column base
    // lane -> row-within-group after the merged butterfly (3-bit bit pattern)
    const int rsel = 4 * (lane & 1) + 2 * ((lane >> 1) & 1) + ((lane >> 2) & 1);

    // ---- stage W_in slice into SMEM ----
    for (int i = tid; i < ROWS * D_IN; i += NTH)
        sWin[i] = Win[(size_t)row0 * D_IN + i];
    __syncthreads();

    // ---- prologue: U[t][row0..row0+15] for all t ----
    for (int it = 0; it < T_SEQ / NTH; ++it) {
        const int t = it * NTH + tid;
        float acc[ROWS];
        #pragma unroll
        for (int r = 0; r < ROWS; ++r) acc[r] = 0.f;
        #pragma unroll
        for (int c = 0; c < 4; ++c) {
            float4 xin[8];
            const float4* ip = (const float4*)(inp + (size_t)t * D_IN + c * 32);
            #pragma unroll
            for (int k = 0; k < 8; ++k) xin[k] = ip[k];
            #pragma unroll
            for (int r = 0; r < ROWS; ++r) {
                const float4* wr = (const float4*)(sWin + r * D_IN + c * 32);
                #pragma unroll
                for (int k = 0; k < 8; ++k) {
                    float4 w = wr[k];
                    acc[r] += w.x * xin[k].x + w.y * xin[k].y
                            + w.z * xin[k].z + w.w * xin[k].w;
                }
            }
        }
        #pragma unroll
        for (int r = 0; r < ROWS; ++r)
            g_U[(size_t)t * N_RES + row0 + r] = acc[r];
    }

    // ---- W_res tile into registers: 8 rows x 8 cols = 64 floats (32 x f32x2) ----
    unsigned long long wv[8][4];
    #pragma unroll
    for (int j = 0; j < 8; ++j) {
        const float* wr = Wres + (size_t)(row0 + 8 * g + j) * N_RES + cb;
        ulonglong2 q0 = *(const ulonglong2*)(wr);
        ulonglong2 q1 = *(const ulonglong2*)(wr + 4);
        wv[j][0] = q0.x; wv[j][1] = q0.y; wv[j][2] = q1.x; wv[j][3] = q1.y;
    }
    __syncthreads();   // g_U complete & visible CTA-wide

    const float cns = 0.022097086912079612f;  // 1/sqrt(2048)
    // flag this lane polls: producer CTA (16*cch + lane) for lanes 0..15
    const unsigned* myflag = &g_flags[((cch << 4) + (lane & 15)) << 5];

    for (int t = 0; t < T_SEQ; ++t) {
        float uval = 0.f;
        if (warp == 0 && lane < ROWS)
            uval = __ldcg(g_U + (size_t)t * N_RES + row0 + lane);   // independent prefetch

        if (t > 0) {
            // ---- per-warp poll: only the 16 producer CTAs of this column chunk ----
            unsigned ok;
            do {
                unsigned f = (lane < 16) ? ld_acq(myflag) : (unsigned)t;
                ok = __all_sync(0xffffffffu, f >= (unsigned)t);
            } while (!ok);

            // ---- this thread's 8 x-values (L2 path, 2x LDG.128) ----
            unsigned long long x0, x1, x2, x3;
            const float* xp = out + (size_t)(t - 1) * N_RES + cb;
            ldcg_v2u64(xp,     x0, x1);
            ldcg_v2u64(xp + 4, x2, x3);

            // ---- 8 rows x 4 packed FMAs ----
            float p[8];
            #pragma unroll
            for (int j = 0; j < 8; ++j) {
                unsigned long long a = ffma2(wv[j][0], x0, 0ull);
                unsigned long long b = ffma2(wv[j][1], x1, 0ull);
                a = ffma2(wv[j][2], x2, a);
                b = ffma2(wv[j][3], x3, b);
                p[j] = hadd2(a) + hadd2(b);
            }

            // ---- merged butterfly: 8 row-sums across 32 lanes in 9 SHFLs ----
            #pragma unroll
            for (int j = 0; j < 4; ++j) {   // xor 1
                float send = (lane & 1) ? p[j] : p[j + 4];
                float recv = __shfl_xor_sync(0xffffffffu, send, 1);
                p[j] = ((lane & 1) ? p[j + 4] : p[j]) + recv;
            }
            #pragma unroll
            for (int j = 0; j < 2; ++j) {   // xor 2
                float send = (lane & 2) ? p[j] : p[j + 2];
                float recv = __shfl_xor_sync(0xffffffffu, send, 2);
                p[j] = ((lane & 2) ? p[j + 2] : p[j]) + recv;
            }
            {                               // xor 4
                float send = (lane & 4) ? p[0] : p[1];
                float recv = __shfl_xor_sync(0xffffffffu, send, 4);
                p[0] = ((lane & 4) ? p[1] : p[0]) + recv;
            }
            p[0] += __shfl_xor_sync(0xffffffffu, p[0], 8);
            p[0] += __shfl_xor_sync(0xffffffffu, p[0], 16);

            if (lane < 8)
                sPart[(8 * g + rsel) * SP_STRIDE + cch] = p[0];
        }
        __syncthreads();                                    // partials ready

        // ---- finishers: warp 0 lanes 0..15, one row each ----
        if (warp == 0 && lane < ROWS) {
            float pre = uval;
            if (t > 0) {
                const float2* pp = (const float2*)(sPart + lane * SP_STRIDE);
                float2 a0 = pp[0], a1 = pp[1], a2 = pp[2], a3 = pp[3];
                pre += ((a0.x + a0.y) + (a1.x + a1.y))
                     + ((a2.x + a2.y) + (a3.x + a3.y));
            }
            __stcg(out + (size_t)t * N_RES + row0 + lane, erff(pre) * cns);
        }
        __syncthreads();                                    // stores done CTA-wide

        if (tid == 0) st_rel(&g_flags[bid << 5], (unsigned)(t + 1));
    }
}

extern "C" void kernel_launch(void* const* d_in, const int* in_sizes, int n_in,
                              void* d_out, int out_size) {
    const float* inp  = (const float*)d_in[0];   // input_data (2048,128)
    const float* Win  = (const float*)d_in[1];   // W_in       (2048,128)
    const float* Wres = (const float*)d_in[2];   // W_res      (2048,2048)
    float* out = (float*)d_out;                  // (2048,2048) float32

    esn_zero_kernel<<<4, 1024>>>();
    esn_kernel<<<GRID, NTH>>>(inp, Win, Wres, out);
}